// round 13
// baseline (speedup 1.0000x reference)
#include <cuda_runtime.h>
#include <math.h>

#define LL 512
#define BB 128
#define DD 512
#define TT 200
#define EE 384
#define CC 128
#define HH 512
#define VV 46
#define G4H 2048
#define NBLK 128
#define NTHR 1024

#define NK8_L0 80
#define NK8_L1 128
#define NK8_L2 128
#define NK8_TOT 336
#define WFRAG_PER_BLK (NK8_TOT * 256)

// smem layout (floats): 8 staging buffers + 4 gate-partial buffers + cell state
#define XBUF   4352             // 32 rows * 136
#define BUFSTRIDE 5376          // XBUF + 1024 (W)
#define GS_OFF 43008            // 8 * 5376
#define CS_OFF 51200            // GS_OFF + 4*2048
#define SMEM_FLOATS 52736       // CS_OFF + 3*512  (= 210.9 KB)

// ---------------- device scratch ----------------
__device__ __align__(128) float g_keyfT[BB * CC * LL];  // [b][c][l]
__device__ __align__(128) float g_valf[BB * LL * CC];   // [b][l][c]
__device__ __align__(128) float g_embW[VV * G4H];
__device__ __align__(128) float g_bias1[G4H];
__device__ __align__(128) float g_bias2[G4H];
__device__ __align__(128) float g_h0T[2][HH * BB];      // [k][b]
__device__ __align__(128) float g_h1T[2][HH * BB];
__device__ __align__(128) float g_h2T[2][HH * BB];
__device__ __align__(128) float g_h2n[BB * HH];         // [b][k]
__device__ __align__(128) float g_ctxT[CC * BB];        // [c][b]
__device__ __align__(128) float g_phiT[HH * CC];        // [k][c]
__device__ __align__(128) float g_wfrag[NBLK * WFRAG_PER_BLK];
__device__ int   g_tok[TT * BB];
__device__ unsigned g_barctr;

__device__ __forceinline__ float sigmoidf_(float x) { return 1.f / (1.f + expf(-x)); }

// runtime split: 2 cheap instructions (LOP3 + FADD)
__device__ __forceinline__ void tsplit(float x, unsigned& h, unsigned& l) {
    unsigned xu = __float_as_uint(x);
    h = xu & 0xFFFFE000u;
    l = __float_as_uint(x - __uint_as_float(h));
}

// precompute-side split (precision-max, off critical path)
__device__ __forceinline__ void tsplit_pre(float x, unsigned& h, unsigned& l) {
    asm("cvt.rna.tf32.f32 %0, %1;" : "=r"(h) : "f"(x));
    float r = x - __uint_as_float(h);
    asm("cvt.rna.tf32.f32 %0, %1;" : "=r"(l) : "f"(r));
}

__device__ __forceinline__ void mma8(float c[4],
    unsigned a0, unsigned a1, unsigned a2, unsigned a3,
    unsigned b0, unsigned b1)
{
    asm volatile("mma.sync.aligned.m16n8k8.row.col.f32.tf32.tf32.f32 "
        "{%0,%1,%2,%3}, {%4,%5,%6,%7}, {%8,%9}, {%0,%1,%2,%3};"
        : "+f"(c[0]), "+f"(c[1]), "+f"(c[2]), "+f"(c[3])
        : "r"(a0), "r"(a1), "r"(a2), "r"(a3), "r"(b0), "r"(b1));
}

// ---------------- warp reductions ----------------
__device__ __forceinline__ float wred_max(float v) {
#pragma unroll
    for (int o = 16; o > 0; o >>= 1) v = fmaxf(v, __shfl_xor_sync(0xFFFFFFFFu, v, o));
    return v;
}
__device__ __forceinline__ float wred_sum(float v) {
#pragma unroll
    for (int o = 16; o > 0; o >>= 1) v += __shfl_xor_sync(0xFFFFFFFFu, v, o);
    return v;
}

// ---------------- grid barrier ----------------
__device__ __forceinline__ void gbar(unsigned& tgt) {
    __syncthreads();
    if (threadIdx.x == 0) {
        asm volatile("red.release.gpu.global.add.u32 [%0], %1;"
                     :: "l"(&g_barctr), "r"(1u) : "memory");
        unsigned v;
        do {
            asm volatile("ld.acquire.gpu.u32 %0, [%1];" : "=r"(v) : "l"(&g_barctr) : "memory");
        } while (v < tgt);
    }
    __syncthreads();
    tgt += NBLK;
}

// ---------------- cp.async ----------------
__device__ __forceinline__ void cp_cg16(float* dst, const float* src) {
    unsigned d = (unsigned)__cvta_generic_to_shared(dst);
    asm volatile("cp.async.cg.shared.global [%0], [%1], 16;" :: "r"(d), "l"(src) : "memory");
}
__device__ __forceinline__ void cp_ca16(float* dst, const float* src) {
    unsigned d = (unsigned)__cvta_generic_to_shared(dst);
    asm volatile("cp.async.ca.shared.global [%0], [%1], 16;" :: "r"(d), "l"(src) : "memory");
}

// stage chunk c (32 k-rows of X, 4 k8 of W) into buffer slot c%8
__device__ __forceinline__ void stage_chunk(float* sm, int c,
    const float* xa, int KA, const float* xh, const float* wfrag)
{
    const int tid = threadIdx.x;
    float* Xb = sm + (c & 7) * BUFSTRIDE;
    {
        int row = tid >> 5;               // 0..31
        int off = (tid & 31) << 2;        // 0..124
        int k = c * 32 + row;
        const float* src = (k < KA) ? (xa + (size_t)k * 128 + off)
                                    : (xh + (size_t)(k - KA) * 128 + off);
        cp_cg16(Xb + row * 136 + off, src);
    }
    if (tid < 256)
        cp_ca16(Xb + XBUF + tid * 4, wfrag + (size_t)c * 1024 + tid * 4);
    asm volatile("cp.async.commit_group;" ::: "memory");
}

// ---------------- one chunk of MMA work (warp handles k8 j = kh) ----------------
__device__ __forceinline__ void compute_chunk(const float* Xb, int kh, int q, int g,
    int nb, int lane, float cA0[4], float cB0[4], float cA1[4], float cB1[4])
{
    const float* Wb = Xb + XBUF;
    const int j = kh;
    float4 w1 = *reinterpret_cast<const float4*>(Wb + j * 256 + lane * 4);
    float4 w2 = *reinterpret_cast<const float4*>(Wb + j * 256 + 128 + lane * 4);
    const unsigned ah0 = __float_as_uint(w1.x), al0 = __float_as_uint(w1.y);
    const unsigned ah1 = __float_as_uint(w1.z), al1 = __float_as_uint(w1.w);
    const unsigned ah2 = __float_as_uint(w2.x), al2 = __float_as_uint(w2.y);
    const unsigned ah3 = __float_as_uint(w2.z), al3 = __float_as_uint(w2.w);
    const int r0 = (j * 8 + q) * 136, r1 = (j * 8 + q + 4) * 136;
    {   // tile 0: batches nb..nb+7
        float x0 = Xb[r0 + nb + g], x1 = Xb[r1 + nb + g];
        unsigned bh0, bl0, bh1, bl1;
        tsplit(x0, bh0, bl0); tsplit(x1, bh1, bl1);
        mma8(cA0, ah0, ah1, ah2, ah3, bh0, bh1);
        mma8(cB0, ah0, ah1, ah2, ah3, bl0, bl1);
        mma8(cA0, al0, al1, al2, al3, bh0, bh1);
    }
    {   // tile 1: batches nb+8..nb+15
        float x0 = Xb[r0 + nb + 8 + g], x1 = Xb[r1 + nb + 8 + g];
        unsigned bh0, bl0, bh1, bl1;
        tsplit(x0, bh0, bl0); tsplit(x1, bh1, bl1);
        mma8(cA1, ah0, ah1, ah2, ah3, bh0, bh1);
        mma8(cB1, ah0, ah1, ah2, ah3, bl0, bl1);
        mma8(cA1, al0, al1, al2, al3, bh0, bh1);
    }
}

// ---------------- LSTM phase ----------------
__device__ void lstm_tc(float* sm, int hhbase,
    const float* xa, int KA, int K, const float* wf,
    const float* xh, const float* pre, const int* tokp,
    float* hoT, float* csm, float* hN)
{
    const int tid = threadIdx.x;
    const int w = tid >> 5, lane = tid & 31;
    const int g = lane >> 2, q = lane & 3;
    const int ng = w & 7, kh = w >> 3;      // 8 batch-groups x 4 K-quarters
    const int nb = ng * 16;
    const int nch = K >> 5;                 // 20 / 32 / 32, divisible by 4

    float cA0[4] = {0.f,0.f,0.f,0.f}, cB0[4] = {0.f,0.f,0.f,0.f};
    float cA1[4] = {0.f,0.f,0.f,0.f}, cB1[4] = {0.f,0.f,0.f,0.f};

    stage_chunk(sm, 0, xa, KA, xh, wf);
    stage_chunk(sm, 1, xa, KA, xh, wf);
    stage_chunk(sm, 2, xa, KA, xh, wf);
    stage_chunk(sm, 3, xa, KA, xh, wf);

    for (int c = 0; c < nch; c += 4) {
        asm volatile("cp.async.wait_group 0;" ::: "memory");
        __syncthreads();
        if (c + 4 < nch) {
            stage_chunk(sm, c + 4, xa, KA, xh, wf);
            stage_chunk(sm, c + 5, xa, KA, xh, wf);
            stage_chunk(sm, c + 6, xa, KA, xh, wf);
            stage_chunk(sm, c + 7, xa, KA, xh, wf);
        }
        compute_chunk(sm + ((c + 0) & 7) * BUFSTRIDE, kh, q, g, nb, lane, cA0, cB0, cA1, cB1);
        compute_chunk(sm + ((c + 1) & 7) * BUFSTRIDE, kh, q, g, nb, lane, cA0, cB0, cA1, cB1);
        compute_chunk(sm + ((c + 2) & 7) * BUFSTRIDE, kh, q, g, nb, lane, cA0, cB0, cA1, cB1);
        compute_chunk(sm + ((c + 3) & 7) * BUFSTRIDE, kh, q, g, nb, lane, cA0, cB0, cA1, cB1);
    }

    // writeback partials into Gs[kh]
    {
        float* Gs = sm + GS_OFF + kh * 2048;
        const int n0 = nb + 2 * q, n1 = nb + 8 + 2 * q;
        *reinterpret_cast<float2*>(&Gs[g * 128 + n0])       = make_float2(cA0[0] + cB0[0], cA0[1] + cB0[1]);
        *reinterpret_cast<float2*>(&Gs[(g + 8) * 128 + n0]) = make_float2(cA0[2] + cB0[2], cA0[3] + cB0[3]);
        *reinterpret_cast<float2*>(&Gs[g * 128 + n1])       = make_float2(cA1[0] + cB1[0], cA1[1] + cB1[1]);
        *reinterpret_cast<float2*>(&Gs[(g + 8) * 128 + n1]) = make_float2(cA1[2] + cB1[2], cA1[3] + cB1[3]);
    }
    __syncthreads();

    // fused reduce(4 kh parts) + bias + nonlinearity: 1 cell per thread (tid<512)
    if (tid < 512) {
        const float* GsA = sm + GS_OFF;
        const int hh = tid >> 7, b = tid & 127;
        const int pbase = tokp ? (__ldg(&tokp[b]) * G4H) : 0;
        float g4[4];
#pragma unroll
        for (int gg = 0; gg < 4; gg++) {
            const int off = (gg * 4 + hh) * 128 + b;
            g4[gg] = __ldg(&pre[pbase + (gg << 9) + hhbase + hh])
                   + GsA[off] + GsA[2048 + off] + GsA[4096 + off] + GsA[6144 + off];
        }
        const float cn = sigmoidf_(g4[1]) * csm[tid] + sigmoidf_(g4[0]) * tanhf(g4[2]);
        const float h = sigmoidf_(g4[3]) * tanhf(cn);
        csm[tid] = cn;
        hoT[(size_t)(hhbase + hh) * 128 + b] = h;
        if (hN) hN[(size_t)b * 512 + hhbase + hh] = h;
    }
    __syncthreads();
}

// ---------------- attention + output projection (1024 threads, block = batch row) ----------------
__device__ void attn5(float* sm, int b, const int* lens, const float* phi_b,
    const float* out_w, const float* out_b,
    float* attn_out, float* logits_out)
{
    float* h2s  = sm;            // 512
    float* qs   = sm + 512;      // 128
    float* part = sm + 640;      // 4096 (32 warps x 128)
    float* as   = sm + 4736;     // 512
    float* ctxs = sm + 5248;     // 128
    float* red  = sm + 5376;     // 64

    const int tid = threadIdx.x;
    const int warp = tid >> 5, lane = tid & 31;

    if (tid < 512) h2s[tid] = __ldcg(&g_h2n[(size_t)b * 512 + tid]);
    __syncthreads();

    // q partials: warp w -> k slice of 16, lane -> 4 c's
    {
        float4 acc = make_float4(0.f, 0.f, 0.f, 0.f);
#pragma unroll 8
        for (int kk = 0; kk < 16; kk++) {
            int k = warp * 16 + kk;
            float hv = h2s[k];
            float4 pv = *reinterpret_cast<const float4*>(&g_phiT[(k << 7) + lane * 4]);
            acc.x = fmaf(hv, pv.x, acc.x); acc.y = fmaf(hv, pv.y, acc.y);
            acc.z = fmaf(hv, pv.z, acc.z); acc.w = fmaf(hv, pv.w, acc.w);
        }
        *reinterpret_cast<float4*>(&part[warp * 128 + lane * 4]) = acc;
    }
    __syncthreads();
    if (tid < 128) {
        float qv = phi_b[tid];
#pragma unroll
        for (int w = 0; w < 32; w++) qv += part[w * 128 + tid];
        qs[tid] = qv;
    }
    __syncthreads();

    // energies: 2 threads per frame (half c-range each), combine via shfl
    const int frame = tid >> 1, half = tid & 1;
    float e;
    {
        const float* kf = g_keyfT + ((size_t)b << 16) + frame;
        const int c0 = half * 64;
        float a0 = 0.f, a1 = 0.f, a2 = 0.f, a3 = 0.f;
#pragma unroll 8
        for (int c = c0; c < c0 + 64; c += 4) {
            a0 = fmaf(__ldcg(kf + ((size_t)(c + 0) << 9)), qs[c + 0], a0);
            a1 = fmaf(__ldcg(kf + ((size_t)(c + 1) << 9)), qs[c + 1], a1);
            a2 = fmaf(__ldcg(kf + ((size_t)(c + 2) << 9)), qs[c + 2], a2);
            a3 = fmaf(__ldcg(kf + ((size_t)(c + 3) << 9)), qs[c + 3], a3);
        }
        e = (a0 + a1) + (a2 + a3);
        e += __shfl_xor_sync(0xFFFFFFFFu, e, 1);   // both halves now hold full energy
    }

    // block max (duplicates are harmless for max)
    {
        float m = wred_max(e);
        if (lane == 0) red[warp] = m;
    }
    __syncthreads();
    if (warp == 0) {
        float v = red[lane];
        v = wred_max(v);
        if (lane == 0) red[32] = v;
    }
    __syncthreads();
    const float mx = red[32];

    const int len = lens[b];
    float p = (frame < len) ? expf(e - mx) : 0.f;
    // sum: count each frame once (half==0 contributes)
    {
        float s = wred_sum((half == 0) ? p : 0.f);
        if (lane == 0) red[warp] = s;
    }
    __syncthreads();
    if (warp == 0) {
        float v = red[lane];
        v = wred_sum(v);
        if (lane == 0) red[33] = v;
    }
    __syncthreads();
    const float inv = 1.f / fmaxf(red[33], 1e-12f);

    const float av = p * inv;
    if (half == 0) {
        as[frame] = av;
        if (attn_out) attn_out[(size_t)b * LL + frame] = av;
    }
    __syncthreads();

    // ctx partials: warp -> l slice of 16, lane -> 4 c's
    {
        float4 acc = make_float4(0.f, 0.f, 0.f, 0.f);
        const float* vf = g_valf + ((size_t)b << 16) + lane * 4;
#pragma unroll 8
        for (int i = 0; i < 16; i++) {
            int l = warp * 16 + i;
            float4 vv = __ldcg(reinterpret_cast<const float4*>(vf + ((size_t)l << 7)));
            float a_ = as[l];
            acc.x = fmaf(vv.x, a_, acc.x); acc.y = fmaf(vv.y, a_, acc.y);
            acc.z = fmaf(vv.z, a_, acc.z); acc.w = fmaf(vv.w, a_, acc.w);
        }
        *reinterpret_cast<float4*>(&part[warp * 128 + lane * 4]) = acc;
    }
    __syncthreads();
    if (tid < 128) {
        float cv = 0.f;
#pragma unroll
        for (int w = 0; w < 32; w++) cv += part[w * 128 + tid];
        ctxs[tid] = cv;
        g_ctxT[tid * 128 + b] = cv;
    }
    __syncthreads();

    if (logits_out) {
        for (int v = warp; v < VV; v += 32) {
            const float* wr = out_w + (size_t)v * (HH + CC);
            float acc = 0.f;
#pragma unroll
            for (int it = 0; it < 5; it++) {
                int k0 = it * 128 + lane * 4;
                float4 wv = *reinterpret_cast<const float4*>(&wr[k0]);
                float4 xv = (it < 4) ? *reinterpret_cast<const float4*>(&h2s[k0])
                                     : *reinterpret_cast<const float4*>(&ctxs[k0 - 512]);
                acc = fmaf(wv.x, xv.x, acc); acc = fmaf(wv.y, xv.y, acc);
                acc = fmaf(wv.z, xv.z, acc); acc = fmaf(wv.w, xv.w, acc);
            }
#pragma unroll
            for (int off = 16; off > 0; off >>= 1)
                acc += __shfl_xor_sync(0xFFFFFFFF, acc, off);
            if (lane == 0) logits_out[(size_t)b * VV + v] = acc + out_b[v];
        }
    }
    __syncthreads();
}

// ---------------- persistent kernel ----------------
__global__ void __launch_bounds__(NTHR, 1) speller_persistent(
    const int* __restrict__ lens, const float* __restrict__ phi_b,
    const float* __restrict__ out_w, const float* __restrict__ out_b,
    const float* __restrict__ cx0, const float* __restrict__ cx1,
    const float* __restrict__ cx2,
    float* __restrict__ attn_base, float* __restrict__ logits_base)
{
    extern __shared__ float smem[];
    float* csm = smem + CS_OFF;

    const int bk = blockIdx.x;
    const int hhbase = bk * 4;
    const int tid = threadIdx.x;
    unsigned tgt = NBLK;

    if (tid < 512) {
        int hh = tid >> 7;
        csm[tid]        = cx0[hhbase + hh];
        csm[512 + tid]  = cx1[hhbase + hh];
        csm[1024 + tid] = cx2[hhbase + hh];
    }
    __syncthreads();

    attn5(smem, bk, lens, phi_b, out_w, out_b, nullptr, nullptr);
    gbar(tgt);

    const float* wf0 = g_wfrag + (size_t)bk * WFRAG_PER_BLK;
    const float* wf1 = wf0 + NK8_L0 * 256;
    const float* wf2 = wf1 + NK8_L1 * 256;

    for (int t = 0; t < TT; t++) {
        const int p = t & 1;
        lstm_tc(smem, hhbase, g_ctxT, 128, 640, wf0,
                g_h0T[p], g_embW, g_tok + (size_t)t * BB,
                g_h0T[p ^ 1], csm, nullptr);
        gbar(tgt);
        lstm_tc(smem, hhbase, g_h0T[p ^ 1], 512, 1024, wf1,
                g_h1T[p], g_bias1, nullptr,
                g_h1T[p ^ 1], csm + 512, nullptr);
        gbar(tgt);
        lstm_tc(smem, hhbase, g_h1T[p ^ 1], 512, 1024, wf2,
                g_h2T[p], g_bias2, nullptr,
                g_h2T[p ^ 1], csm + 1024, g_h2n);
        gbar(tgt);
        attn5(smem, bk, lens, phi_b, out_w, out_b,
              attn_base + (size_t)t * BB * LL,
              logits_base + (size_t)t * BB * VV);
        gbar(tgt);
    }
}

// ================= fused precompute (one kernel, role dispatch) =================

__device__ void keyval_role(int bid,
    const float* __restrict__ lf,
    const float* __restrict__ key_w, const float* __restrict__ key_b,
    const float* __restrict__ value_w, const float* __restrict__ value_b)
{
    __shared__ __align__(16) float As[16][64];
    __shared__ __align__(16) float Bs[16][64];

    const int tid = threadIdx.x;
    const int m0 = (bid & 1023) * 64;
    const int n0 = (bid >> 10) * 64;
    const int ty = tid >> 4;
    const int tx = tid & 15;

    float acc[4][4];
#pragma unroll
    for (int i = 0; i < 4; i++)
#pragma unroll
        for (int j = 0; j < 4; j++) acc[i][j] = 0.f;

    const int mi = tid >> 2;
    const int kq = (tid & 3) * 4;

    for (int kb = 0; kb < DD; kb += 16) {
        {
            float4 v = *reinterpret_cast<const float4*>(&lf[(size_t)(m0 + mi) * DD + kb + kq]);
            As[kq + 0][mi] = v.x; As[kq + 1][mi] = v.y; As[kq + 2][mi] = v.z; As[kq + 3][mi] = v.w;
        }
        {
            int n = n0 + mi;
            const float* wrow = (n < CC) ? (key_w + (size_t)n * DD) : (value_w + (size_t)(n - CC) * DD);
            float4 v = *reinterpret_cast<const float4*>(&wrow[kb + kq]);
            Bs[kq + 0][mi] = v.x; Bs[kq + 1][mi] = v.y; Bs[kq + 2][mi] = v.z; Bs[kq + 3][mi] = v.w;
        }
        __syncthreads();
#pragma unroll
        for (int k = 0; k < 16; k++) {
            float4 av = *reinterpret_cast<const float4*>(&As[k][ty * 4]);
            float4 bv = *reinterpret_cast<const float4*>(&Bs[k][tx * 4]);
            float aa[4] = {av.x, av.y, av.z, av.w};
            float bb[4] = {bv.x, bv.y, bv.z, bv.w};
#pragma unroll
            for (int i = 0; i < 4; i++)
#pragma unroll
                for (int j = 0; j < 4; j++) acc[i][j] = fmaf(aa[i], bb[j], acc[i][j]);
        }
        __syncthreads();
    }

#pragma unroll
    for (int i = 0; i < 4; i++) {
        int m = m0 + ty * 4 + i;
        int l = m >> 7, b = m & 127;
#pragma unroll
        for (int j = 0; j < 4; j++) {
            int n = n0 + tx * 4 + j;
            if (n < CC)
                g_keyfT[((size_t)b << 16) + (size_t)n * 512 + l] = acc[i][j] + key_b[n];
            else
                g_valf[((size_t)b << 16) + (size_t)l * CC + (n - CC)] = acc[i][j] + value_b[n - CC];
        }
    }
}

__device__ void embw_role(int v,
    const float* __restrict__ emb, const float* __restrict__ w_ih0,
    const float* __restrict__ b_ih0, const float* __restrict__ b_hh0)
{
    __shared__ float es[EE];
    const int tid = threadIdx.x;
    for (int i = tid; i < EE; i += 256) es[i] = emb[(size_t)v * EE + i];
    __syncthreads();
    for (int j = tid; j < G4H; j += 256) {
        const float* wr = w_ih0 + (size_t)j * (EE + CC);
        float a0 = b_ih0[j] + b_hh0[j], a1 = 0.f, a2 = 0.f, a3 = 0.f;
        for (int e = 0; e < EE; e += 4) {
            a0 = fmaf(es[e + 0], wr[e + 0], a0);
            a1 = fmaf(es[e + 1], wr[e + 1], a1);
            a2 = fmaf(es[e + 2], wr[e + 2], a2);
            a3 = fmaf(es[e + 3], wr[e + 3], a3);
        }
        g_embW[(size_t)v * G4H + j] = a0 + a1 + a2 + a3;
    }
}

// per k8 (256 floats): [piece p 0/1][lane 32][i 0..3]
//   col = bq + ((i>=2)?8:0), kk = j*8 + kq + (p?4:0), hilo = i&1
__device__ void whl_role(int blk,
    const float* __restrict__ wih0, const float* __restrict__ whh0,
    const float* __restrict__ wih1, const float* __restrict__ whh1,
    const float* __restrict__ wih2, const float* __restrict__ whh2)
{
    float* dst = g_wfrag + (size_t)blk * WFRAG_PER_BLK;

    for (int idx = threadIdx.x; idx < WFRAG_PER_BLK; idx += 256) {
        int j8 = idx >> 8;
        int rem = idx & 255;
        int p = rem >> 7;
        int lane = (rem >> 2) & 31;
        int i = rem & 3;
        int kq = lane & 3, bq = lane >> 2;
        int col = bq + ((i >= 2) ? 8 : 0);
        int hilo = i & 1;
        int jrow = ((col >> 2) << 9) + blk * 4 + (col & 3);

        int layer, j;
        if (j8 < NK8_L0)               { layer = 0; j = j8; }
        else if (j8 < NK8_L0 + NK8_L1) { layer = 1; j = j8 - NK8_L0; }
        else                           { layer = 2; j = j8 - NK8_L0 - NK8_L1; }
        int kk = j * 8 + kq + (p ? 4 : 0);

        float v;
        if (layer == 0)
            v = (kk < 128) ? wih0[(size_t)jrow * (EE + CC) + EE + kk]
                           : whh0[(size_t)jrow * 512 + kk - 128];
        else if (layer == 1)
            v = (kk < 512) ? wih1[(size_t)jrow * 512 + kk]
                           : whh1[(size_t)jrow * 512 + kk - 512];
        else
            v = (kk < 512) ? wih2[(size_t)jrow * 512 + kk]
                           : whh2[(size_t)jrow * 512 + kk - 512];

        unsigned h, l; tsplit_pre(v, h, l);
        dst[idx] = __uint_as_float(hilo ? l : h);
    }
}

__device__ void misc_role(int rb,
    const float* __restrict__ bi1, const float* __restrict__ bh1,
    const float* __restrict__ bi2, const float* __restrict__ bh2,
    const float* __restrict__ phi_w, const int* __restrict__ transcript,
    const float* __restrict__ hx0, const float* __restrict__ hx1,
    const float* __restrict__ hx2)
{
    int i = rb * 256 + threadIdx.x;
    if (i == 0) g_barctr = 0;
    if (i < G4H) { g_bias1[i] = bi1[i] + bh1[i]; g_bias2[i] = bi2[i] + bh2[i]; }
    if (i < HH * CC) {
        int k = i >> 7, c = i & 127;
        g_phiT[i] = phi_w[(size_t)c * HH + k];
    }
    if (i < TT * BB) {
        int t = i / BB, b = i % BB;
        g_tok[i] = (t == 0) ? 0 : transcript[(size_t)(t - 1) * BB + b];
    }
    if (i < HH * BB) {
        int k = i >> 7, b = i & 127;
        g_h0T[0][i] = hx0[k];
        g_h1T[0][i] = hx1[k];
        g_h2T[0][i] = hx2[k];
        g_h2n[(size_t)b * HH + k] = hx2[k];
    }
}

__global__ void __launch_bounds__(256) pre_kernel(
    const float* lf,
    const float* key_w, const float* key_b,
    const float* value_w, const float* value_b,
    const float* emb, const float* w_ih0,
    const float* b_ih0, const float* b_hh0,
    const float* w_hh0,
    const float* w_ih1, const float* w_hh1,
    const float* w_ih2, const float* w_hh2,
    const float* bi1, const float* bh1,
    const float* bi2, const float* bh2,
    const float* phi_w, const int* transcript,
    const float* hx0, const float* hx1, const float* hx2)
{
    const int bid = blockIdx.x;
    if (bid < 4096)
        keyval_role(bid, lf, key_w, key_b, value_w, value_b);
    else if (bid < 4096 + VV)
        embw_role(bid - 4096, emb, w_ih0, b_ih0, b_hh0);
    else if (bid < 4096 + VV + NBLK)
        whl_role(bid - 4096 - VV, w_ih0, w_hh0, w_ih1, w_hh1, w_ih2, w_hh2);
    else
        misc_role(bid - 4096 - VV - NBLK, bi1, bh1, bi2, bh2, phi_w, transcript,
                  hx0, hx1, hx2);
}

// ---------------- launch ----------------
extern "C" void kernel_launch(void* const* d_in, const int* in_sizes, int n_in,
                              void* d_out, int out_size)
{
    const float* lf         = (const float*)d_in[0];
    const int*   lens       = (const int*)  d_in[1];
    const int*   transcript = (const int*)  d_in[2];
    const float* emb        = (const float*)d_in[3];
    const float* w_ih0 = (const float*)d_in[4];
    const float* w_hh0 = (const float*)d_in[5];
    const float* b_ih0 = (const float*)d_in[6];
    const float* b_hh0 = (const float*)d_in[7];
    const float* w_ih1 = (const float*)d_in[8];
    const float* w_hh1 = (const float*)d_in[9];
    const float* b_ih1 = (const float*)d_in[10];
    const float* b_hh1 = (const float*)d_in[11];
    const float* w_ih2 = (const float*)d_in[12];
    const float* w_hh2 = (const float*)d_in[13];
    const float* b_ih2 = (const float*)d_in[14];
    const float* b_hh2 = (const float*)d_in[15];
    const float* phi_w = (const float*)d_in[16];
    const float* phi_b = (const float*)d_in[17];
    const float* key_w = (const float*)d_in[18];
    const float* key_b = (const float*)d_in[19];
    const float* value_w = (const float*)d_in[20];
    const float* value_b = (const float*)d_in[21];
    const float* out_w = (const float*)d_in[22];
    const float* out_b = (const float*)d_in[23];
    const float* hx0 = (const float*)d_in[24];
    const float* cx0 = (const float*)d_in[25];
    const float* hx1 = (const float*)d_in[26];
    const float* cx1 = (const float*)d_in[27];
    const float* hx2 = (const float*)d_in[28];
    const float* cx2 = (const float*)d_in[29];

    float* out = (float*)d_out;
    float* logits_base = out;                        // [T,B,V]
    float* attn_base   = out + (size_t)TT * BB * VV; // [T,B,L]

    const int smem_bytes = SMEM_FLOATS * 4;
    cudaFuncSetAttribute(speller_persistent,
                         cudaFuncAttributeMaxDynamicSharedMemorySize, smem_bytes);

    pre_kernel<<<4096 + VV + NBLK + 256, 256>>>(
        lf, key_w, key_b, value_w, value_b,
        emb, w_ih0, b_ih0, b_hh0, w_hh0,
        w_ih1, w_hh1, w_ih2, w_hh2,
        b_ih1, b_hh1, b_ih2, b_hh2,
        phi_w, transcript, hx0, hx1, hx2);
    speller_persistent<<<NBLK, NTHR, smem_bytes>>>(
        lens, phi_b, out_w, out_b, cx0, cx1, cx2,
        attn_base, logits_base);
}

// round 14
// speedup vs baseline: 1.0970x; 1.0970x over previous
#include <cuda_runtime.h>
#include <math.h>

#define LL 512
#define BB 128
#define DD 512
#define TT 200
#define EE 384
#define CC 128
#define HH 512
#define VV 46
#define G4H 2048
#define NBLK 128
#define NTHR 512

#define NK8_L0 80
#define NK8_L1 128
#define NK8_L2 128
#define NK8_TOT 336
#define WFRAG_PER_BLK (NK8_TOT * 256)

// smem layout (floats): 8 staging buffers + 4 gate-partial buffers + cell state
#define XBUF   4352             // 32 rows * 136
#define BUFSTRIDE 5376          // XBUF + 1024 (W)
#define GS_OFF 43008            // 8 * 5376
#define CS_OFF 51200            // GS_OFF + 4*2048
#define SMEM_FLOATS 52736       // CS_OFF + 3*512  (= 210.9 KB)

// ---------------- device scratch ----------------
__device__ __align__(128) float g_keyfT[BB * CC * LL];  // [b][c][l]
__device__ __align__(128) float g_valf[BB * LL * CC];   // [b][l][c]
__device__ __align__(128) float g_embW[VV * G4H];
__device__ __align__(128) float g_bias1[G4H];
__device__ __align__(128) float g_bias2[G4H];
__device__ __align__(128) float g_h0T[2][HH * BB];      // [k][b]
__device__ __align__(128) float g_h1T[2][HH * BB];
__device__ __align__(128) float g_h2T[2][HH * BB];
__device__ __align__(128) float g_h2n[BB * HH];         // [b][k]
__device__ __align__(128) float g_ctxT[CC * BB];        // [c][b]
__device__ __align__(128) float g_phiT[HH * CC];        // [k][c]
__device__ __align__(128) float g_wfrag[NBLK * WFRAG_PER_BLK];
__device__ int   g_tok[TT * BB];
__device__ unsigned g_barctr;

__device__ __forceinline__ float sigmoidf_(float x) { return 1.f / (1.f + expf(-x)); }

// runtime split: 2 cheap instructions (LOP3 + FADD)
__device__ __forceinline__ void tsplit(float x, unsigned& h, unsigned& l) {
    unsigned xu = __float_as_uint(x);
    h = xu & 0xFFFFE000u;
    l = __float_as_uint(x - __uint_as_float(h));
}

// precompute-side split (precision-max, off critical path)
__device__ __forceinline__ void tsplit_pre(float x, unsigned& h, unsigned& l) {
    asm("cvt.rna.tf32.f32 %0, %1;" : "=r"(h) : "f"(x));
    float r = x - __uint_as_float(h);
    asm("cvt.rna.tf32.f32 %0, %1;" : "=r"(l) : "f"(r));
}

__device__ __forceinline__ void mma8(float c[4],
    unsigned a0, unsigned a1, unsigned a2, unsigned a3,
    unsigned b0, unsigned b1)
{
    asm volatile("mma.sync.aligned.m16n8k8.row.col.f32.tf32.tf32.f32 "
        "{%0,%1,%2,%3}, {%4,%5,%6,%7}, {%8,%9}, {%0,%1,%2,%3};"
        : "+f"(c[0]), "+f"(c[1]), "+f"(c[2]), "+f"(c[3])
        : "r"(a0), "r"(a1), "r"(a2), "r"(a3), "r"(b0), "r"(b1));
}

// ---------------- warp reductions ----------------
__device__ __forceinline__ float wred_max(float v) {
#pragma unroll
    for (int o = 16; o > 0; o >>= 1) v = fmaxf(v, __shfl_xor_sync(0xFFFFFFFFu, v, o));
    return v;
}
__device__ __forceinline__ float wred_sum(float v) {
#pragma unroll
    for (int o = 16; o > 0; o >>= 1) v += __shfl_xor_sync(0xFFFFFFFFu, v, o);
    return v;
}

// ---------------- grid barrier ----------------
__device__ __forceinline__ void gbar(unsigned& tgt) {
    __syncthreads();
    if (threadIdx.x == 0) {
        asm volatile("red.release.gpu.global.add.u32 [%0], %1;"
                     :: "l"(&g_barctr), "r"(1u) : "memory");
        unsigned v;
        do {
            asm volatile("ld.acquire.gpu.u32 %0, [%1];" : "=r"(v) : "l"(&g_barctr) : "memory");
        } while (v < tgt);
    }
    __syncthreads();
    tgt += NBLK;
}

// ---------------- cp.async ----------------
__device__ __forceinline__ void cp_cg16(float* dst, const float* src) {
    unsigned d = (unsigned)__cvta_generic_to_shared(dst);
    asm volatile("cp.async.cg.shared.global [%0], [%1], 16;" :: "r"(d), "l"(src) : "memory");
}
__device__ __forceinline__ void cp_ca16(float* dst, const float* src) {
    unsigned d = (unsigned)__cvta_generic_to_shared(dst);
    asm volatile("cp.async.ca.shared.global [%0], [%1], 16;" :: "r"(d), "l"(src) : "memory");
}

// stage chunk c (32 k-rows of X, 4 k8 of W) into buffer slot c%8
__device__ __forceinline__ void stage_chunk(float* sm, int c,
    const float* xa, int KA, const float* xh, const float* wfrag)
{
    const int tid = threadIdx.x;
    float* Xb = sm + (c & 7) * BUFSTRIDE;
#pragma unroll
    for (int i = 0; i < 2; i++) {
        int idx = tid + i * 512;
        int row = idx >> 5;
        int off = (idx & 31) << 2;
        int k = c * 32 + row;
        const float* src = (k < KA) ? (xa + (size_t)k * 128 + off)
                                    : (xh + (size_t)(k - KA) * 128 + off);
        cp_cg16(Xb + row * 136 + off, src);
    }
    if (tid < 256)
        cp_ca16(Xb + XBUF + tid * 4, wfrag + (size_t)c * 1024 + tid * 4);
    asm volatile("cp.async.commit_group;" ::: "memory");
}

// ---------------- one chunk of MMA work (warp handles k8 j, 4 batch tiles) ----------------
__device__ __forceinline__ void compute_chunk(const float* Xb, int j, int q, int g,
    int nb, int lane, float acc[4][4])
{
    const float* Wb = Xb + XBUF;
    float4 w1 = *reinterpret_cast<const float4*>(Wb + j * 256 + lane * 4);
    float4 w2 = *reinterpret_cast<const float4*>(Wb + j * 256 + 128 + lane * 4);
    const unsigned ah0 = __float_as_uint(w1.x), al0 = __float_as_uint(w1.y);
    const unsigned ah1 = __float_as_uint(w1.z), al1 = __float_as_uint(w1.w);
    const unsigned ah2 = __float_as_uint(w2.x), al2 = __float_as_uint(w2.y);
    const unsigned ah3 = __float_as_uint(w2.z), al3 = __float_as_uint(w2.w);
    const int r0 = (j * 8 + q) * 136, r1 = (j * 8 + q + 4) * 136;
#pragma unroll
    for (int t = 0; t < 4; t++) {
        const int nt = nb + t * 8;
        float x0 = Xb[r0 + nt + g], x1 = Xb[r1 + nt + g];
        unsigned bh0, bl0, bh1, bl1;
        tsplit(x0, bh0, bl0); tsplit(x1, bh1, bl1);
        mma8(acc[t], ah0, ah1, ah2, ah3, bh0, bh1);
        mma8(acc[t], ah0, ah1, ah2, ah3, bl0, bl1);
        mma8(acc[t], al0, al1, al2, al3, bh0, bh1);
    }
}

// ---------------- LSTM phase ----------------
__device__ void lstm_tc(float* sm, int hhbase,
    const float* xa, int KA, int K, const float* wf,
    const float* xh, const float* pre, const int* tokp,
    float* hoT, float* csm, float* hN)
{
    const int tid = threadIdx.x;
    const int w = tid >> 5, lane = tid & 31;
    const int g = lane >> 2, q = lane & 3;
    const int ng = w & 3, kh = w >> 2;      // 4 batch-groups (32 b) x 4 K-quarters
    const int nb = ng * 32;
    const int nch = K >> 5;                 // 20 / 32 / 32, divisible by 4

    float acc[4][4];
#pragma unroll
    for (int t = 0; t < 4; t++)
#pragma unroll
        for (int i = 0; i < 4; i++) acc[t][i] = 0.f;

    stage_chunk(sm, 0, xa, KA, xh, wf);
    stage_chunk(sm, 1, xa, KA, xh, wf);
    stage_chunk(sm, 2, xa, KA, xh, wf);
    stage_chunk(sm, 3, xa, KA, xh, wf);

    for (int c = 0; c < nch; c += 4) {
        asm volatile("cp.async.wait_group 0;" ::: "memory");
        __syncthreads();
        if (c + 4 < nch) {
            stage_chunk(sm, c + 4, xa, KA, xh, wf);
            stage_chunk(sm, c + 5, xa, KA, xh, wf);
            stage_chunk(sm, c + 6, xa, KA, xh, wf);
            stage_chunk(sm, c + 7, xa, KA, xh, wf);
        }
        compute_chunk(sm + ((c + 0) & 7) * BUFSTRIDE, kh, q, g, nb, lane, acc);
        compute_chunk(sm + ((c + 1) & 7) * BUFSTRIDE, kh, q, g, nb, lane, acc);
        compute_chunk(sm + ((c + 2) & 7) * BUFSTRIDE, kh, q, g, nb, lane, acc);
        compute_chunk(sm + ((c + 3) & 7) * BUFSTRIDE, kh, q, g, nb, lane, acc);
    }

    // writeback partials into Gs[kh]
    {
        float* Gs = sm + GS_OFF + kh * 2048;
#pragma unroll
        for (int t = 0; t < 4; t++) {
            const int n0 = nb + t * 8 + 2 * q;
            *reinterpret_cast<float2*>(&Gs[g * 128 + n0])       = make_float2(acc[t][0], acc[t][1]);
            *reinterpret_cast<float2*>(&Gs[(g + 8) * 128 + n0]) = make_float2(acc[t][2], acc[t][3]);
        }
    }
    __syncthreads();

    // fused reduce(4 kh parts) + bias + nonlinearity: 1 cell per thread
    {
        const float* GsA = sm + GS_OFF;
        const int hh = tid >> 7, b = tid & 127;
        const int pbase = tokp ? (__ldg(&tokp[b]) * G4H) : 0;
        float g4[4];
#pragma unroll
        for (int gg = 0; gg < 4; gg++) {
            const int off = (gg * 4 + hh) * 128 + b;
            g4[gg] = __ldg(&pre[pbase + (gg << 9) + hhbase + hh])
                   + (GsA[off] + GsA[2048 + off]) + (GsA[4096 + off] + GsA[6144 + off]);
        }
        const float cn = sigmoidf_(g4[1]) * csm[tid] + sigmoidf_(g4[0]) * tanhf(g4[2]);
        const float h = sigmoidf_(g4[3]) * tanhf(cn);
        csm[tid] = cn;
        hoT[(size_t)(hhbase + hh) * 128 + b] = h;
        if (hN) hN[(size_t)b * 512 + hhbase + hh] = h;
    }
    __syncthreads();
}

// ---------------- attention + output projection (512 threads, block = batch row) ----------------
__device__ void attn5(float* sm, int b, const int* lens, const float* phi_b,
    const float* out_w, const float* out_b,
    float* attn_out, float* logits_out)
{
    float* h2s  = sm;            // 512
    float* qs   = sm + 512;      // 128
    float* part = sm + 640;      // 2048
    float* as   = sm + 2688;     // 512
    float* ctxs = sm + 3200;     // 128
    float* red  = sm + 3328;     // 32

    const int tid = threadIdx.x;
    const int warp = tid >> 5, lane = tid & 31;

    h2s[tid] = __ldcg(&g_h2n[(size_t)b * 512 + tid]);
    __syncthreads();

    // q partials
    {
        float4 acc = make_float4(0.f, 0.f, 0.f, 0.f);
#pragma unroll 8
        for (int kk = 0; kk < 32; kk++) {
            int k = warp * 32 + kk;
            float hv = h2s[k];
            float4 pv = *reinterpret_cast<const float4*>(&g_phiT[(k << 7) + lane * 4]);
            acc.x = fmaf(hv, pv.x, acc.x); acc.y = fmaf(hv, pv.y, acc.y);
            acc.z = fmaf(hv, pv.z, acc.z); acc.w = fmaf(hv, pv.w, acc.w);
        }
        *reinterpret_cast<float4*>(&part[warp * 128 + lane * 4]) = acc;
    }
    __syncthreads();
    if (tid < 128) {
        float qv = phi_b[tid];
#pragma unroll
        for (int w = 0; w < 16; w++) qv += part[w * 128 + tid];
        qs[tid] = qv;
    }
    __syncthreads();

    // energies: 1 frame per thread
    float e;
    {
        const float* kf = g_keyfT + ((size_t)b << 16) + tid;
        float a0 = 0.f, a1 = 0.f, a2 = 0.f, a3 = 0.f;
#pragma unroll 8
        for (int c = 0; c < 128; c += 4) {
            a0 = fmaf(__ldcg(kf + ((size_t)(c + 0) << 9)), qs[c + 0], a0);
            a1 = fmaf(__ldcg(kf + ((size_t)(c + 1) << 9)), qs[c + 1], a1);
            a2 = fmaf(__ldcg(kf + ((size_t)(c + 2) << 9)), qs[c + 2], a2);
            a3 = fmaf(__ldcg(kf + ((size_t)(c + 3) << 9)), qs[c + 3], a3);
        }
        e = (a0 + a1) + (a2 + a3);
    }

    // max reduce
    {
        float m = wred_max(e);
        if (lane == 0) red[warp] = m;
    }
    __syncthreads();
    if (warp == 0) {
        float v = (lane < 16) ? red[lane] : -3.4e38f;
        v = wred_max(v);
        if (lane == 0) red[16] = v;
    }
    __syncthreads();
    const float mx = red[16];

    const int len = lens[b];
    float p = (tid < len) ? expf(e - mx) : 0.f;

    // sum reduce
    {
        float s = wred_sum(p);
        if (lane == 0) red[warp] = s;
    }
    __syncthreads();
    if (warp == 0) {
        float v = (lane < 16) ? red[lane] : 0.f;
        v = wred_sum(v);
        if (lane == 0) red[17] = v;
    }
    __syncthreads();
    const float inv = 1.f / fmaxf(red[17], 1e-12f);

    const float av = p * inv;
    as[tid] = av;
    if (attn_out) attn_out[(size_t)b * LL + tid] = av;
    __syncthreads();

    // ctx partials
    {
        float4 acc = make_float4(0.f, 0.f, 0.f, 0.f);
        const float* vf = g_valf + ((size_t)b << 16) + lane * 4;
#pragma unroll 8
        for (int i = 0; i < 32; i++) {
            int l = warp * 32 + i;
            float4 vv = __ldcg(reinterpret_cast<const float4*>(vf + ((size_t)l << 7)));
            float a_ = as[l];
            acc.x = fmaf(vv.x, a_, acc.x); acc.y = fmaf(vv.y, a_, acc.y);
            acc.z = fmaf(vv.z, a_, acc.z); acc.w = fmaf(vv.w, a_, acc.w);
        }
        *reinterpret_cast<float4*>(&part[warp * 128 + lane * 4]) = acc;
    }
    __syncthreads();
    if (tid < 128) {
        float cv = 0.f;
#pragma unroll
        for (int w = 0; w < 16; w++) cv += part[w * 128 + tid];
        ctxs[tid] = cv;
        g_ctxT[tid * 128 + b] = cv;
    }
    __syncthreads();

    if (logits_out) {
        for (int v = warp; v < VV; v += 16) {
            const float* wr = out_w + (size_t)v * (HH + CC);
            float acc = 0.f;
#pragma unroll
            for (int it = 0; it < 5; it++) {
                int k0 = it * 128 + lane * 4;
                float4 wv = *reinterpret_cast<const float4*>(&wr[k0]);
                float4 xv = (it < 4) ? *reinterpret_cast<const float4*>(&h2s[k0])
                                     : *reinterpret_cast<const float4*>(&ctxs[k0 - 512]);
                acc = fmaf(wv.x, xv.x, acc); acc = fmaf(wv.y, xv.y, acc);
                acc = fmaf(wv.z, xv.z, acc); acc = fmaf(wv.w, xv.w, acc);
            }
#pragma unroll
            for (int off = 16; off > 0; off >>= 1)
                acc += __shfl_xor_sync(0xFFFFFFFF, acc, off);
            if (lane == 0) logits_out[(size_t)b * VV + v] = acc + out_b[v];
        }
    }
    __syncthreads();
}

// ---------------- persistent kernel ----------------
__global__ void __launch_bounds__(NTHR, 1) speller_persistent(
    const int* __restrict__ lens, const float* __restrict__ phi_b,
    const float* __restrict__ out_w, const float* __restrict__ out_b,
    const float* __restrict__ cx0, const float* __restrict__ cx1,
    const float* __restrict__ cx2,
    float* __restrict__ attn_base, float* __restrict__ logits_base)
{
    extern __shared__ float smem[];
    float* csm = smem + CS_OFF;

    const int bk = blockIdx.x;
    const int hhbase = bk * 4;
    const int tid = threadIdx.x;
    unsigned tgt = NBLK;

    {
        int hh = tid >> 7;
        csm[tid]        = cx0[hhbase + hh];
        csm[512 + tid]  = cx1[hhbase + hh];
        csm[1024 + tid] = cx2[hhbase + hh];
    }
    __syncthreads();

    attn5(smem, bk, lens, phi_b, out_w, out_b, nullptr, nullptr);
    gbar(tgt);

    const float* wf0 = g_wfrag + (size_t)bk * WFRAG_PER_BLK;
    const float* wf1 = wf0 + NK8_L0 * 256;
    const float* wf2 = wf1 + NK8_L1 * 256;

    for (int t = 0; t < TT; t++) {
        const int p = t & 1;
        lstm_tc(smem, hhbase, g_ctxT, 128, 640, wf0,
                g_h0T[p], g_embW, g_tok + (size_t)t * BB,
                g_h0T[p ^ 1], csm, nullptr);
        gbar(tgt);
        lstm_tc(smem, hhbase, g_h0T[p ^ 1], 512, 1024, wf1,
                g_h1T[p], g_bias1, nullptr,
                g_h1T[p ^ 1], csm + 512, nullptr);
        gbar(tgt);
        lstm_tc(smem, hhbase, g_h1T[p ^ 1], 512, 1024, wf2,
                g_h2T[p], g_bias2, nullptr,
                g_h2T[p ^ 1], csm + 1024, g_h2n);
        gbar(tgt);
        attn5(smem, bk, lens, phi_b, out_w, out_b,
              attn_base + (size_t)t * BB * LL,
              logits_base + (size_t)t * BB * VV);
        gbar(tgt);
    }
}

// ================= fused precompute (one kernel, role dispatch) =================

__device__ void keyval_role(int bid,
    const float* __restrict__ lf,
    const float* __restrict__ key_w, const float* __restrict__ key_b,
    const float* __restrict__ value_w, const float* __restrict__ value_b)
{
    __shared__ __align__(16) float As[16][64];
    __shared__ __align__(16) float Bs[16][64];

    const int tid = threadIdx.x;
    const int m0 = (bid & 1023) * 64;
    const int n0 = (bid >> 10) * 64;
    const int ty = tid >> 4;
    const int tx = tid & 15;

    float acc[4][4];
#pragma unroll
    for (int i = 0; i < 4; i++)
#pragma unroll
        for (int j = 0; j < 4; j++) acc[i][j] = 0.f;

    const int mi = tid >> 2;
    const int kq = (tid & 3) * 4;

    for (int kb = 0; kb < DD; kb += 16) {
        {
            float4 v = *reinterpret_cast<const float4*>(&lf[(size_t)(m0 + mi) * DD + kb + kq]);
            As[kq + 0][mi] = v.x; As[kq + 1][mi] = v.y; As[kq + 2][mi] = v.z; As[kq + 3][mi] = v.w;
        }
        {
            int n = n0 + mi;
            const float* wrow = (n < CC) ? (key_w + (size_t)n * DD) : (value_w + (size_t)(n - CC) * DD);
            float4 v = *reinterpret_cast<const float4*>(&wrow[kb + kq]);
            Bs[kq + 0][mi] = v.x; Bs[kq + 1][mi] = v.y; Bs[kq + 2][mi] = v.z; Bs[kq + 3][mi] = v.w;
        }
        __syncthreads();
#pragma unroll
        for (int k = 0; k < 16; k++) {
            float4 av = *reinterpret_cast<const float4*>(&As[k][ty * 4]);
            float4 bv = *reinterpret_cast<const float4*>(&Bs[k][tx * 4]);
            float aa[4] = {av.x, av.y, av.z, av.w};
            float bb[4] = {bv.x, bv.y, bv.z, bv.w};
#pragma unroll
            for (int i = 0; i < 4; i++)
#pragma unroll
                for (int j = 0; j < 4; j++) acc[i][j] = fmaf(aa[i], bb[j], acc[i][j]);
        }
        __syncthreads();
    }

#pragma unroll
    for (int i = 0; i < 4; i++) {
        int m = m0 + ty * 4 + i;
        int l = m >> 7, b = m & 127;
#pragma unroll
        for (int j = 0; j < 4; j++) {
            int n = n0 + tx * 4 + j;
            if (n < CC)
                g_keyfT[((size_t)b << 16) + (size_t)n * 512 + l] = acc[i][j] + key_b[n];
            else
                g_valf[((size_t)b << 16) + (size_t)l * CC + (n - CC)] = acc[i][j] + value_b[n - CC];
        }
    }
}

__device__ void embw_role(int v,
    const float* __restrict__ emb, const float* __restrict__ w_ih0,
    const float* __restrict__ b_ih0, const float* __restrict__ b_hh0)
{
    __shared__ float es[EE];
    const int tid = threadIdx.x;
    for (int i = tid; i < EE; i += 256) es[i] = emb[(size_t)v * EE + i];
    __syncthreads();
    for (int j = tid; j < G4H; j += 256) {
        const float* wr = w_ih0 + (size_t)j * (EE + CC);
        float a0 = b_ih0[j] + b_hh0[j], a1 = 0.f, a2 = 0.f, a3 = 0.f;
        for (int e = 0; e < EE; e += 4) {
            a0 = fmaf(es[e + 0], wr[e + 0], a0);
            a1 = fmaf(es[e + 1], wr[e + 1], a1);
            a2 = fmaf(es[e + 2], wr[e + 2], a2);
            a3 = fmaf(es[e + 3], wr[e + 3], a3);
        }
        g_embW[(size_t)v * G4H + j] = a0 + a1 + a2 + a3;
    }
}

// per k8 (256 floats): [piece p 0/1][lane 32][i 0..3]
//   col = bq + ((i>=2)?8:0), kk = j*8 + kq + (p?4:0), hilo = i&1
__device__ void whl_role(int blk,
    const float* __restrict__ wih0, const float* __restrict__ whh0,
    const float* __restrict__ wih1, const float* __restrict__ whh1,
    const float* __restrict__ wih2, const float* __restrict__ whh2)
{
    float* dst = g_wfrag + (size_t)blk * WFRAG_PER_BLK;

    for (int idx = threadIdx.x; idx < WFRAG_PER_BLK; idx += 256) {
        int j8 = idx >> 8;
        int rem = idx & 255;
        int p = rem >> 7;
        int lane = (rem >> 2) & 31;
        int i = rem & 3;
        int kq = lane & 3, bq = lane >> 2;
        int col = bq + ((i >= 2) ? 8 : 0);
        int hilo = i & 1;
        int jrow = ((col >> 2) << 9) + blk * 4 + (col & 3);

        int layer, j;
        if (j8 < NK8_L0)               { layer = 0; j = j8; }
        else if (j8 < NK8_L0 + NK8_L1) { layer = 1; j = j8 - NK8_L0; }
        else                           { layer = 2; j = j8 - NK8_L0 - NK8_L1; }
        int kk = j * 8 + kq + (p ? 4 : 0);

        float v;
        if (layer == 0)
            v = (kk < 128) ? wih0[(size_t)jrow * (EE + CC) + EE + kk]
                           : whh0[(size_t)jrow * 512 + kk - 128];
        else if (layer == 1)
            v = (kk < 512) ? wih1[(size_t)jrow * 512 + kk]
                           : whh1[(size_t)jrow * 512 + kk - 512];
        else
            v = (kk < 512) ? wih2[(size_t)jrow * 512 + kk]
                           : whh2[(size_t)jrow * 512 + kk - 512];

        unsigned h, l; tsplit_pre(v, h, l);
        dst[idx] = __uint_as_float(hilo ? l : h);
    }
}

__device__ void misc_role(int rb,
    const float* __restrict__ bi1, const float* __restrict__ bh1,
    const float* __restrict__ bi2, const float* __restrict__ bh2,
    const float* __restrict__ phi_w, const int* __restrict__ transcript,
    const float* __restrict__ hx0, const float* __restrict__ hx1,
    const float* __restrict__ hx2)
{
    int i = rb * 256 + threadIdx.x;
    if (i == 0) g_barctr = 0;
    if (i < G4H) { g_bias1[i] = bi1[i] + bh1[i]; g_bias2[i] = bi2[i] + bh2[i]; }
    if (i < HH * CC) {
        int k = i >> 7, c = i & 127;
        g_phiT[i] = phi_w[(size_t)c * HH + k];
    }
    if (i < TT * BB) {
        int t = i / BB, b = i % BB;
        g_tok[i] = (t == 0) ? 0 : transcript[(size_t)(t - 1) * BB + b];
    }
    if (i < HH * BB) {
        int k = i >> 7, b = i & 127;
        g_h0T[0][i] = hx0[k];
        g_h1T[0][i] = hx1[k];
        g_h2T[0][i] = hx2[k];
        g_h2n[(size_t)b * HH + k] = hx2[k];
    }
}

__global__ void __launch_bounds__(256) pre_kernel(
    const float* lf,
    const float* key_w, const float* key_b,
    const float* value_w, const float* value_b,
    const float* emb, const float* w_ih0,
    const float* b_ih0, const float* b_hh0,
    const float* w_hh0,
    const float* w_ih1, const float* w_hh1,
    const float* w_ih2, const float* w_hh2,
    const float* bi1, const float* bh1,
    const float* bi2, const float* bh2,
    const float* phi_w, const int* transcript,
    const float* hx0, const float* hx1, const float* hx2)
{
    const int bid = blockIdx.x;
    if (bid < 4096)
        keyval_role(bid, lf, key_w, key_b, value_w, value_b);
    else if (bid < 4096 + VV)
        embw_role(bid - 4096, emb, w_ih0, b_ih0, b_hh0);
    else if (bid < 4096 + VV + NBLK)
        whl_role(bid - 4096 - VV, w_ih0, w_hh0, w_ih1, w_hh1, w_ih2, w_hh2);
    else
        misc_role(bid - 4096 - VV - NBLK, bi1, bh1, bi2, bh2, phi_w, transcript,
                  hx0, hx1, hx2);
}

// ---------------- launch ----------------
extern "C" void kernel_launch(void* const* d_in, const int* in_sizes, int n_in,
                              void* d_out, int out_size)
{
    const float* lf         = (const float*)d_in[0];
    const int*   lens       = (const int*)  d_in[1];
    const int*   transcript = (const int*)  d_in[2];
    const float* emb        = (const float*)d_in[3];
    const float* w_ih0 = (const float*)d_in[4];
    const float* w_hh0 = (const float*)d_in[5];
    const float* b_ih0 = (const float*)d_in[6];
    const float* b_hh0 = (const float*)d_in[7];
    const float* w_ih1 = (const float*)d_in[8];
    const float* w_hh1 = (const float*)d_in[9];
    const float* b_ih1 = (const float*)d_in[10];
    const float* b_hh1 = (const float*)d_in[11];
    const float* w_ih2 = (const float*)d_in[12];
    const float* w_hh2 = (const float*)d_in[13];
    const float* b_ih2 = (const float*)d_in[14];
    const float* b_hh2 = (const float*)d_in[15];
    const float* phi_w = (const float*)d_in[16];
    const float* phi_b = (const float*)d_in[17];
    const float* key_w = (const float*)d_in[18];
    const float* key_b = (const float*)d_in[19];
    const float* value_w = (const float*)d_in[20];
    const float* value_b = (const float*)d_in[21];
    const float* out_w = (const float*)d_in[22];
    const float* out_b = (const float*)d_in[23];
    const float* hx0 = (const float*)d_in[24];
    const float* cx0 = (const float*)d_in[25];
    const float* hx1 = (const float*)d_in[26];
    const float* cx1 = (const float*)d_in[27];
    const float* hx2 = (const float*)d_in[28];
    const float* cx2 = (const float*)d_in[29];

    float* out = (float*)d_out;
    float* logits_base = out;                        // [T,B,V]
    float* attn_base   = out + (size_t)TT * BB * VV; // [T,B,L]

    const int smem_bytes = SMEM_FLOATS * 4;
    cudaFuncSetAttribute(speller_persistent,
                         cudaFuncAttributeMaxDynamicSharedMemorySize, smem_bytes);

    pre_kernel<<<4096 + VV + NBLK + 256, 256>>>(
        lf, key_w, key_b, value_w, value_b,
        emb, w_ih0, b_ih0, b_hh0, w_hh0,
        w_ih1, w_hh1, w_ih2, w_hh2,
        b_ih1, b_hh1, b_ih2, b_hh2,
        phi_w, transcript, hx0, hx1, hx2);
    speller_persistent<<<NBLK, NTHR, smem_bytes>>>(
        lens, phi_b, out_w, out_b, cx0, cx1, cx2,
        attn_base, logits_base);
}

// round 15
// speedup vs baseline: 1.1635x; 1.0607x over previous
#include <cuda_runtime.h>
#include <math.h>

#define LL 512
#define BB 128
#define DD 512
#define TT 200
#define EE 384
#define CC 128
#define HH 512
#define VV 46
#define G4H 2048
#define NBLK 128
#define NTHR 512

#define NK8_L0 80
#define NK8_L1 128
#define NK8_L2 128
#define NK8_TOT 336
#define WFRAG_PER_BLK (NK8_TOT * 256)

// smem layout (floats): 8 staging buffers + 2 gate-partial buffers + cell state
#define XBUF   4352             // 32 rows * 136
#define BUFSTRIDE 5376          // XBUF + 1024 (W)
#define GS_OFF 43008            // 8 * 5376
#define CS_OFF 47104            // GS_OFF + 2*2048
#define SMEM_FLOATS 48640       // CS_OFF + 3*512  (= 194.6 KB)

// ---------------- device scratch ----------------
__device__ __align__(128) float g_keyfT[BB * CC * LL];  // [b][c][l]
__device__ __align__(128) float g_valf[BB * LL * CC];   // [b][l][c]
__device__ __align__(128) float g_embW[VV * G4H];
__device__ __align__(128) float g_bias1[G4H];
__device__ __align__(128) float g_bias2[G4H];
__device__ __align__(128) float g_h0T[2][HH * BB];      // [k][b]
__device__ __align__(128) float g_h1T[2][HH * BB];
__device__ __align__(128) float g_h2T[2][HH * BB];
__device__ __align__(128) float g_h2n[BB * HH];         // [b][k]
__device__ __align__(128) float g_ctxT[CC * BB];        // [c][b]
__device__ __align__(128) float g_phiT[HH * CC];        // [k][c]
__device__ __align__(128) float g_wfrag[NBLK * WFRAG_PER_BLK];
__device__ int   g_tok[TT * BB];
__device__ unsigned g_barctr;

__device__ __forceinline__ float sigmoidf_(float x) { return 1.f / (1.f + expf(-x)); }

// runtime split: 2 cheap instructions (LOP3 + FADD)
__device__ __forceinline__ void tsplit(float x, unsigned& h, unsigned& l) {
    unsigned xu = __float_as_uint(x);
    h = xu & 0xFFFFE000u;
    l = __float_as_uint(x - __uint_as_float(h));
}

// precompute-side split (precision-max, off critical path)
__device__ __forceinline__ void tsplit_pre(float x, unsigned& h, unsigned& l) {
    asm("cvt.rna.tf32.f32 %0, %1;" : "=r"(h) : "f"(x));
    float r = x - __uint_as_float(h);
    asm("cvt.rna.tf32.f32 %0, %1;" : "=r"(l) : "f"(r));
}

__device__ __forceinline__ void mma8(float c[4],
    unsigned a0, unsigned a1, unsigned a2, unsigned a3,
    unsigned b0, unsigned b1)
{
    asm volatile("mma.sync.aligned.m16n8k8.row.col.f32.tf32.tf32.f32 "
        "{%0,%1,%2,%3}, {%4,%5,%6,%7}, {%8,%9}, {%0,%1,%2,%3};"
        : "+f"(c[0]), "+f"(c[1]), "+f"(c[2]), "+f"(c[3])
        : "r"(a0), "r"(a1), "r"(a2), "r"(a3), "r"(b0), "r"(b1));
}

// ---------------- warp reductions ----------------
__device__ __forceinline__ float wred_max(float v) {
#pragma unroll
    for (int o = 16; o > 0; o >>= 1) v = fmaxf(v, __shfl_xor_sync(0xFFFFFFFFu, v, o));
    return v;
}
__device__ __forceinline__ float wred_sum(float v) {
#pragma unroll
    for (int o = 16; o > 0; o >>= 1) v += __shfl_xor_sync(0xFFFFFFFFu, v, o);
    return v;
}

// ---------------- grid barrier ----------------
__device__ __forceinline__ void gbar(unsigned& tgt) {
    __syncthreads();
    if (threadIdx.x == 0) {
        asm volatile("red.release.gpu.global.add.u32 [%0], %1;"
                     :: "l"(&g_barctr), "r"(1u) : "memory");
        unsigned v;
        do {
            asm volatile("ld.acquire.gpu.u32 %0, [%1];" : "=r"(v) : "l"(&g_barctr) : "memory");
        } while (v < tgt);
    }
    __syncthreads();
    tgt += NBLK;
}

// ---------------- cp.async ----------------
__device__ __forceinline__ void cp_cg16(float* dst, const float* src) {
    unsigned d = (unsigned)__cvta_generic_to_shared(dst);
    asm volatile("cp.async.cg.shared.global [%0], [%1], 16;" :: "r"(d), "l"(src) : "memory");
}
__device__ __forceinline__ void cp_ca16(float* dst, const float* src) {
    unsigned d = (unsigned)__cvta_generic_to_shared(dst);
    asm volatile("cp.async.ca.shared.global [%0], [%1], 16;" :: "r"(d), "l"(src) : "memory");
}

// prefetch W of next phase's chunks 0-3 into slots 0-3 W areas (16 KB)
// safe: called after the previous phase's epilogue __syncthreads (all slot reads done),
// and the attention phase never touches the W sub-areas.
__device__ __forceinline__ void prefetch_w(float* sm, const float* wf)
{
    const int tid = threadIdx.x;
#pragma unroll
    for (int i = 0; i < 2; i++) {
        int job = tid + i * 512;           // 0..1023
        int c = job >> 8;                  // chunk 0..3
        int off = (job & 255) * 4;         // float offset
        cp_ca16(sm + c * BUFSTRIDE + XBUF + off, wf + (size_t)c * 1024 + off);
    }
    asm volatile("cp.async.commit_group;" ::: "memory");
}

// stage chunk c (32 k-rows of X, 4 k8 of W) into buffer slot c%8
__device__ __forceinline__ void stage_chunk(float* sm, int c,
    const float* xa, int KA, const float* xh, const float* wfrag, int skipw)
{
    const int tid = threadIdx.x;
    float* Xb = sm + (c & 7) * BUFSTRIDE;
#pragma unroll
    for (int i = 0; i < 2; i++) {
        int idx = tid + i * 512;
        int row = idx >> 5;
        int off = (idx & 31) << 2;
        int k = c * 32 + row;
        const float* src = (k < KA) ? (xa + (size_t)k * 128 + off)
                                    : (xh + (size_t)(k - KA) * 128 + off);
        cp_cg16(Xb + row * 136 + off, src);
    }
    if (!skipw && tid < 256)
        cp_ca16(Xb + XBUF + tid * 4, wfrag + (size_t)c * 1024 + tid * 4);
    asm volatile("cp.async.commit_group;" ::: "memory");
}

// ---------------- one chunk of MMA work ----------------
__device__ __forceinline__ void compute_chunk(const float* Xb, int kh, int q, int g,
    int nb, int lane, float cA0[4], float cB0[4], float cA1[4], float cB1[4])
{
    const float* Wb = Xb + XBUF;
#pragma unroll
    for (int jj = 0; jj < 2; jj++) {
        const int j = kh * 2 + jj;
        float4 w1 = *reinterpret_cast<const float4*>(Wb + j * 256 + lane * 4);
        float4 w2 = *reinterpret_cast<const float4*>(Wb + j * 256 + 128 + lane * 4);
        const unsigned ah0 = __float_as_uint(w1.x), al0 = __float_as_uint(w1.y);
        const unsigned ah1 = __float_as_uint(w1.z), al1 = __float_as_uint(w1.w);
        const unsigned ah2 = __float_as_uint(w2.x), al2 = __float_as_uint(w2.y);
        const unsigned ah3 = __float_as_uint(w2.z), al3 = __float_as_uint(w2.w);
        const int r0 = (j * 8 + q) * 136, r1 = (j * 8 + q + 4) * 136;
        {   // tile 0: batches nb..nb+7
            float x0 = Xb[r0 + nb + g], x1 = Xb[r1 + nb + g];
            unsigned bh0, bl0, bh1, bl1;
            tsplit(x0, bh0, bl0); tsplit(x1, bh1, bl1);
            mma8(cA0, ah0, ah1, ah2, ah3, bh0, bh1);
            mma8(cB0, ah0, ah1, ah2, ah3, bl0, bl1);
            mma8(cA0, al0, al1, al2, al3, bh0, bh1);
        }
        {   // tile 1: batches nb+8..nb+15
            float x0 = Xb[r0 + nb + 8 + g], x1 = Xb[r1 + nb + 8 + g];
            unsigned bh0, bl0, bh1, bl1;
            tsplit(x0, bh0, bl0); tsplit(x1, bh1, bl1);
            mma8(cA1, ah0, ah1, ah2, ah3, bh0, bh1);
            mma8(cB1, ah0, ah1, ah2, ah3, bl0, bl1);
            mma8(cA1, al0, al1, al2, al3, bh0, bh1);
        }
    }
}

// ---------------- LSTM phase ----------------
__device__ void lstm_tc(float* sm, int hhbase,
    const float* xa, int KA, int K, const float* wf,
    const float* xh, const float* pre, const int* tokp,
    float* hoT, float* csm, float* hN, int wpre)
{
    const int tid = threadIdx.x;
    const int w = tid >> 5, lane = tid & 31;
    const int g = lane >> 2, q = lane & 3;
    const int ng = w & 7, kh = w >> 3;
    const int nb = ng * 16;
    const int nch = K >> 5;        // 20 / 32 / 32, divisible by 4

    float cA0[4] = {0.f,0.f,0.f,0.f}, cB0[4] = {0.f,0.f,0.f,0.f};
    float cA1[4] = {0.f,0.f,0.f,0.f}, cB1[4] = {0.f,0.f,0.f,0.f};

    stage_chunk(sm, 0, xa, KA, xh, wf, wpre);
    stage_chunk(sm, 1, xa, KA, xh, wf, wpre);
    stage_chunk(sm, 2, xa, KA, xh, wf, wpre);
    stage_chunk(sm, 3, xa, KA, xh, wf, wpre);

    for (int c = 0; c < nch; c += 4) {
        asm volatile("cp.async.wait_group 0;" ::: "memory");
        __syncthreads();
        if (c + 4 < nch) {
            stage_chunk(sm, c + 4, xa, KA, xh, wf, 0);
            stage_chunk(sm, c + 5, xa, KA, xh, wf, 0);
            stage_chunk(sm, c + 6, xa, KA, xh, wf, 0);
            stage_chunk(sm, c + 7, xa, KA, xh, wf, 0);
        }
        compute_chunk(sm + ((c + 0) & 7) * BUFSTRIDE, kh, q, g, nb, lane, cA0, cB0, cA1, cB1);
        compute_chunk(sm + ((c + 1) & 7) * BUFSTRIDE, kh, q, g, nb, lane, cA0, cB0, cA1, cB1);
        compute_chunk(sm + ((c + 2) & 7) * BUFSTRIDE, kh, q, g, nb, lane, cA0, cB0, cA1, cB1);
        compute_chunk(sm + ((c + 3) & 7) * BUFSTRIDE, kh, q, g, nb, lane, cA0, cB0, cA1, cB1);
    }

    // writeback partials into Gs[kh]
    {
        float* Gs = sm + GS_OFF + kh * 2048;
        const int n0 = nb + 2 * q, n1 = nb + 8 + 2 * q;
        *reinterpret_cast<float2*>(&Gs[g * 128 + n0])       = make_float2(cA0[0] + cB0[0], cA0[1] + cB0[1]);
        *reinterpret_cast<float2*>(&Gs[(g + 8) * 128 + n0]) = make_float2(cA0[2] + cB0[2], cA0[3] + cB0[3]);
        *reinterpret_cast<float2*>(&Gs[g * 128 + n1])       = make_float2(cA1[0] + cB1[0], cA1[1] + cB1[1]);
        *reinterpret_cast<float2*>(&Gs[(g + 8) * 128 + n1]) = make_float2(cA1[2] + cB1[2], cA1[3] + cB1[3]);
    }
    __syncthreads();

    // fused reduce + bias + nonlinearity: 1 cell per thread
    {
        const float* GsA = sm + GS_OFF;
        const int hh = tid >> 7, b = tid & 127;
        const int pbase = tokp ? (__ldg(&tokp[b]) * G4H) : 0;
        float g4[4];
#pragma unroll
        for (int gg = 0; gg < 4; gg++) {
            const int off = (gg * 4 + hh) * 128 + b;
            g4[gg] = __ldg(&pre[pbase + (gg << 9) + hhbase + hh]) + GsA[off] + GsA[2048 + off];
        }
        const float cn = sigmoidf_(g4[1]) * csm[tid] + sigmoidf_(g4[0]) * tanhf(g4[2]);
        const float h = sigmoidf_(g4[3]) * tanhf(cn);
        csm[tid] = cn;
        hoT[(size_t)(hhbase + hh) * 128 + b] = h;
        if (hN) hN[(size_t)b * 512 + hhbase + hh] = h;
    }
    __syncthreads();
}

// ---------------- attention + output projection (512 threads, block = batch row) ----------------
__device__ void attn5(float* sm, int b, const int* lens, const float* phi_b,
    const float* out_w, const float* out_b,
    float* attn_out, float* logits_out)
{
    float* h2s  = sm;            // 512
    float* qs   = sm + 512;      // 128
    float* part = sm + 640;      // 2048
    float* as   = sm + 2688;     // 512
    float* ctxs = sm + 3200;     // 128
    float* red  = sm + 3328;     // 32

    const int tid = threadIdx.x;
    const int warp = tid >> 5, lane = tid & 31;

    h2s[tid] = __ldcg(&g_h2n[(size_t)b * 512 + tid]);
    __syncthreads();

    // q partials
    {
        float4 acc = make_float4(0.f, 0.f, 0.f, 0.f);
#pragma unroll 8
        for (int kk = 0; kk < 32; kk++) {
            int k = warp * 32 + kk;
            float hv = h2s[k];
            float4 pv = *reinterpret_cast<const float4*>(&g_phiT[(k << 7) + lane * 4]);
            acc.x = fmaf(hv, pv.x, acc.x); acc.y = fmaf(hv, pv.y, acc.y);
            acc.z = fmaf(hv, pv.z, acc.z); acc.w = fmaf(hv, pv.w, acc.w);
        }
        *reinterpret_cast<float4*>(&part[warp * 128 + lane * 4]) = acc;
    }
    __syncthreads();
    if (tid < 128) {
        float qv = phi_b[tid];
#pragma unroll
        for (int w = 0; w < 16; w++) qv += part[w * 128 + tid];
        qs[tid] = qv;
    }
    __syncthreads();

    // energies: 1 frame per thread
    float e;
    {
        const float* kf = g_keyfT + ((size_t)b << 16) + tid;
        float a0 = 0.f, a1 = 0.f, a2 = 0.f, a3 = 0.f;
#pragma unroll 8
        for (int c = 0; c < 128; c += 4) {
            a0 = fmaf(__ldcg(kf + ((size_t)(c + 0) << 9)), qs[c + 0], a0);
            a1 = fmaf(__ldcg(kf + ((size_t)(c + 1) << 9)), qs[c + 1], a1);
            a2 = fmaf(__ldcg(kf + ((size_t)(c + 2) << 9)), qs[c + 2], a2);
            a3 = fmaf(__ldcg(kf + ((size_t)(c + 3) << 9)), qs[c + 3], a3);
        }
        e = (a0 + a1) + (a2 + a3);
    }

    // max reduce
    {
        float m = wred_max(e);
        if (lane == 0) red[warp] = m;
    }
    __syncthreads();
    if (warp == 0) {
        float v = (lane < 16) ? red[lane] : -3.4e38f;
        v = wred_max(v);
        if (lane == 0) red[16] = v;
    }
    __syncthreads();
    const float mx = red[16];

    const int len = lens[b];
    float p = (tid < len) ? expf(e - mx) : 0.f;

    // sum reduce
    {
        float s = wred_sum(p);
        if (lane == 0) red[warp] = s;
    }
    __syncthreads();
    if (warp == 0) {
        float v = (lane < 16) ? red[lane] : 0.f;
        v = wred_sum(v);
        if (lane == 0) red[17] = v;
    }
    __syncthreads();
    const float inv = 1.f / fmaxf(red[17], 1e-12f);

    const float av = p * inv;
    as[tid] = av;
    if (attn_out) __stcs(&attn_out[(size_t)b * LL + tid], av);
    __syncthreads();

    // ctx partials
    {
        float4 acc = make_float4(0.f, 0.f, 0.f, 0.f);
        const float* vf = g_valf + ((size_t)b << 16) + lane * 4;
#pragma unroll 8
        for (int i = 0; i < 32; i++) {
            int l = warp * 32 + i;
            float4 vv = __ldcg(reinterpret_cast<const float4*>(vf + ((size_t)l << 7)));
            float a_ = as[l];
            acc.x = fmaf(vv.x, a_, acc.x); acc.y = fmaf(vv.y, a_, acc.y);
            acc.z = fmaf(vv.z, a_, acc.z); acc.w = fmaf(vv.w, a_, acc.w);
        }
        *reinterpret_cast<float4*>(&part[warp * 128 + lane * 4]) = acc;
    }
    __syncthreads();
    if (tid < 128) {
        float cv = 0.f;
#pragma unroll
        for (int w = 0; w < 16; w++) cv += part[w * 128 + tid];
        ctxs[tid] = cv;
        g_ctxT[tid * 128 + b] = cv;
    }
    __syncthreads();

    if (logits_out) {
        for (int v = warp; v < VV; v += 16) {
            const float* wr = out_w + (size_t)v * (HH + CC);
            float acc = 0.f;
#pragma unroll
            for (int it = 0; it < 5; it++) {
                int k0 = it * 128 + lane * 4;
                float4 wv = *reinterpret_cast<const float4*>(&wr[k0]);
                float4 xv = (it < 4) ? *reinterpret_cast<const float4*>(&h2s[k0])
                                     : *reinterpret_cast<const float4*>(&ctxs[k0 - 512]);
                acc = fmaf(wv.x, xv.x, acc); acc = fmaf(wv.y, xv.y, acc);
                acc = fmaf(wv.z, xv.z, acc); acc = fmaf(wv.w, xv.w, acc);
            }
#pragma unroll
            for (int off = 16; off > 0; off >>= 1)
                acc += __shfl_xor_sync(0xFFFFFFFF, acc, off);
            if (lane == 0) __stcs(&logits_out[(size_t)b * VV + v], acc + out_b[v]);
        }
    }
    __syncthreads();
}

// ---------------- persistent kernel ----------------
__global__ void __launch_bounds__(NTHR, 1) speller_persistent(
    const int* __restrict__ lens, const float* __restrict__ phi_b,
    const float* __restrict__ out_w, const float* __restrict__ out_b,
    const float* __restrict__ cx0, const float* __restrict__ cx1,
    const float* __restrict__ cx2,
    float* __restrict__ attn_base, float* __restrict__ logits_base)
{
    extern __shared__ float smem[];
    float* csm = smem + CS_OFF;

    const int bk = blockIdx.x;
    const int hhbase = bk * 4;
    const int tid = threadIdx.x;
    unsigned tgt = NBLK;

    {
        int hh = tid >> 7;
        csm[tid]        = cx0[hhbase + hh];
        csm[512 + tid]  = cx1[hhbase + hh];
        csm[1024 + tid] = cx2[hhbase + hh];
    }
    __syncthreads();

    const float* wf0 = g_wfrag + (size_t)bk * WFRAG_PER_BLK;
    const float* wf1 = wf0 + NK8_L0 * 256;
    const float* wf2 = wf1 + NK8_L1 * 256;

    // prefetch L0's first W chunks; lands during initial attention
    prefetch_w(smem, wf0);

    attn5(smem, bk, lens, phi_b, out_w, out_b, nullptr, nullptr);
    gbar(tgt);

    for (int t = 0; t < TT; t++) {
        const int p = t & 1;
        lstm_tc(smem, hhbase, g_ctxT, 128, 640, wf0,
                g_h0T[p], g_embW, g_tok + (size_t)t * BB,
                g_h0T[p ^ 1], csm, nullptr, 1);
        prefetch_w(smem, wf1);          // lands during gbar
        gbar(tgt);
        lstm_tc(smem, hhbase, g_h0T[p ^ 1], 512, 1024, wf1,
                g_h1T[p], g_bias1, nullptr,
                g_h1T[p ^ 1], csm + 512, nullptr, 1);
        prefetch_w(smem, wf2);
        gbar(tgt);
        lstm_tc(smem, hhbase, g_h1T[p ^ 1], 512, 1024, wf2,
                g_h2T[p], g_bias2, nullptr,
                g_h2T[p ^ 1], csm + 1024, g_h2n, 1);
        prefetch_w(smem, wf0);          // lands during gbar + attention
        gbar(tgt);
        attn5(smem, bk, lens, phi_b, out_w, out_b,
              attn_base + (size_t)t * BB * LL,
              logits_base + (size_t)t * BB * VV);
        gbar(tgt);
    }
}

// ================= fused precompute (one kernel, role dispatch) =================

__device__ void keyval_role(int bid,
    const float* __restrict__ lf,
    const float* __restrict__ key_w, const float* __restrict__ key_b,
    const float* __restrict__ value_w, const float* __restrict__ value_b)
{
    __shared__ __align__(16) float As[16][64];
    __shared__ __align__(16) float Bs[16][64];

    const int tid = threadIdx.x;
    const int m0 = (bid & 1023) * 64;
    const int n0 = (bid >> 10) * 64;
    const int ty = tid >> 4;
    const int tx = tid & 15;

    float acc[4][4];
#pragma unroll
    for (int i = 0; i < 4; i++)
#pragma unroll
        for (int j = 0; j < 4; j++) acc[i][j] = 0.f;

    const int mi = tid >> 2;
    const int kq = (tid & 3) * 4;

    for (int kb = 0; kb < DD; kb += 16) {
        {
            float4 v = *reinterpret_cast<const float4*>(&lf[(size_t)(m0 + mi) * DD + kb + kq]);
            As[kq + 0][mi] = v.x; As[kq + 1][mi] = v.y; As[kq + 2][mi] = v.z; As[kq + 3][mi] = v.w;
        }
        {
            int n = n0 + mi;
            const float* wrow = (n < CC) ? (key_w + (size_t)n * DD) : (value_w + (size_t)(n - CC) * DD);
            float4 v = *reinterpret_cast<const float4*>(&wrow[kb + kq]);
            Bs[kq + 0][mi] = v.x; Bs[kq + 1][mi] = v.y; Bs[kq + 2][mi] = v.z; Bs[kq + 3][mi] = v.w;
        }
        __syncthreads();
#pragma unroll
        for (int k = 0; k < 16; k++) {
            float4 av = *reinterpret_cast<const float4*>(&As[k][ty * 4]);
            float4 bv = *reinterpret_cast<const float4*>(&Bs[k][tx * 4]);
            float aa[4] = {av.x, av.y, av.z, av.w};
            float bb[4] = {bv.x, bv.y, bv.z, bv.w};
#pragma unroll
            for (int i = 0; i < 4; i++)
#pragma unroll
                for (int j = 0; j < 4; j++) acc[i][j] = fmaf(aa[i], bb[j], acc[i][j]);
        }
        __syncthreads();
    }

#pragma unroll
    for (int i = 0; i < 4; i++) {
        int m = m0 + ty * 4 + i;
        int l = m >> 7, b = m & 127;
#pragma unroll
        for (int j = 0; j < 4; j++) {
            int n = n0 + tx * 4 + j;
            if (n < CC)
                g_keyfT[((size_t)b << 16) + (size_t)n * 512 + l] = acc[i][j] + key_b[n];
            else
                g_valf[((size_t)b << 16) + (size_t)l * CC + (n - CC)] = acc[i][j] + value_b[n - CC];
        }
    }
}

__device__ void embw_role(int v,
    const float* __restrict__ emb, const float* __restrict__ w_ih0,
    const float* __restrict__ b_ih0, const float* __restrict__ b_hh0)
{
    __shared__ float es[EE];
    const int tid = threadIdx.x;
    for (int i = tid; i < EE; i += 256) es[i] = emb[(size_t)v * EE + i];
    __syncthreads();
    for (int j = tid; j < G4H; j += 256) {
        const float* wr = w_ih0 + (size_t)j * (EE + CC);
        float a0 = b_ih0[j] + b_hh0[j], a1 = 0.f, a2 = 0.f, a3 = 0.f;
        for (int e = 0; e < EE; e += 4) {
            a0 = fmaf(es[e + 0], wr[e + 0], a0);
            a1 = fmaf(es[e + 1], wr[e + 1], a1);
            a2 = fmaf(es[e + 2], wr[e + 2], a2);
            a3 = fmaf(es[e + 3], wr[e + 3], a3);
        }
        g_embW[(size_t)v * G4H + j] = a0 + a1 + a2 + a3;
    }
}

// per k8 (256 floats): [piece p 0/1][lane 32][i 0..3]
//   col = bq + ((i>=2)?8:0), kk = j*8 + kq + (p?4:0), hilo = i&1
__device__ void whl_role(int blk,
    const float* __restrict__ wih0, const float* __restrict__ whh0,
    const float* __restrict__ wih1, const float* __restrict__ whh1,
    const float* __restrict__ wih2, const float* __restrict__ whh2)
{
    float* dst = g_wfrag + (size_t)blk * WFRAG_PER_BLK;

    for (int idx = threadIdx.x; idx < WFRAG_PER_BLK; idx += 256) {
        int j8 = idx >> 8;
        int rem = idx & 255;
        int p = rem >> 7;
        int lane = (rem >> 2) & 31;
        int i = rem & 3;
        int kq = lane & 3, bq = lane >> 2;
        int col = bq + ((i >= 2) ? 8 : 0);
        int hilo = i & 1;
        int jrow = ((col >> 2) << 9) + blk * 4 + (col & 3);

        int layer, j;
        if (j8 < NK8_L0)               { layer = 0; j = j8; }
        else if (j8 < NK8_L0 + NK8_L1) { layer = 1; j = j8 - NK8_L0; }
        else                           { layer = 2; j = j8 - NK8_L0 - NK8_L1; }
        int kk = j * 8 + kq + (p ? 4 : 0);

        float v;
        if (layer == 0)
            v = (kk < 128) ? wih0[(size_t)jrow * (EE + CC) + EE + kk]
                           : whh0[(size_t)jrow * 512 + kk - 128];
        else if (layer == 1)
            v = (kk < 512) ? wih1[(size_t)jrow * 512 + kk]
                           : whh1[(size_t)jrow * 512 + kk - 512];
        else
            v = (kk < 512) ? wih2[(size_t)jrow * 512 + kk]
                           : whh2[(size_t)jrow * 512 + kk - 512];

        unsigned h, l; tsplit_pre(v, h, l);
        dst[idx] = __uint_as_float(hilo ? l : h);
    }
}

__device__ void misc_role(int rb,
    const float* __restrict__ bi1, const float* __restrict__ bh1,
    const float* __restrict__ bi2, const float* __restrict__ bh2,
    const float* __restrict__ phi_w, const int* __restrict__ transcript,
    const float* __restrict__ hx0, const float* __restrict__ hx1,
    const float* __restrict__ hx2)
{
    int i = rb * 256 + threadIdx.x;
    if (i == 0) g_barctr = 0;
    if (i < G4H) { g_bias1[i] = bi1[i] + bh1[i]; g_bias2[i] = bi2[i] + bh2[i]; }
    if (i < HH * CC) {
        int k = i >> 7, c = i & 127;
        g_phiT[i] = phi_w[(size_t)c * HH + k];
    }
    if (i < TT * BB) {
        int t = i / BB, b = i % BB;
        g_tok[i] = (t == 0) ? 0 : transcript[(size_t)(t - 1) * BB + b];
    }
    if (i < HH * BB) {
        int k = i >> 7, b = i & 127;
        g_h0T[0][i] = hx0[k];
        g_h1T[0][i] = hx1[k];
        g_h2T[0][i] = hx2[k];
        g_h2n[(size_t)b * HH + k] = hx2[k];
    }
}

__global__ void __launch_bounds__(256) pre_kernel(
    const float* lf,
    const float* key_w, const float* key_b,
    const float* value_w, const float* value_b,
    const float* emb, const float* w_ih0,
    const float* b_ih0, const float* b_hh0,
    const float* w_hh0,
    const float* w_ih1, const float* w_hh1,
    const float* w_ih2, const float* w_hh2,
    const float* bi1, const float* bh1,
    const float* bi2, const float* bh2,
    const float* phi_w, const int* transcript,
    const float* hx0, const float* hx1, const float* hx2)
{
    const int bid = blockIdx.x;
    if (bid < 4096)
        keyval_role(bid, lf, key_w, key_b, value_w, value_b);
    else if (bid < 4096 + VV)
        embw_role(bid - 4096, emb, w_ih0, b_ih0, b_hh0);
    else if (bid < 4096 + VV + NBLK)
        whl_role(bid - 4096 - VV, w_ih0, w_hh0, w_ih1, w_hh1, w_ih2, w_hh2);
    else
        misc_role(bid - 4096 - VV - NBLK, bi1, bh1, bi2, bh2, phi_w, transcript,
                  hx0, hx1, hx2);
}

// ---------------- launch ----------------
extern "C" void kernel_launch(void* const* d_in, const int* in_sizes, int n_in,
                              void* d_out, int out_size)
{
    const float* lf         = (const float*)d_in[0];
    const int*   lens       = (const int*)  d_in[1];
    const int*   transcript = (const int*)  d_in[2];
    const float* emb        = (const float*)d_in[3];
    const float* w_ih0 = (const float*)d_in[4];
    const float* w_hh0 = (const float*)d_in[5];
    const float* b_ih0 = (const float*)d_in[6];
    const float* b_hh0 = (const float*)d_in[7];
    const float* w_ih1 = (const float*)d_in[8];
    const float* w_hh1 = (const float*)d_in[9];
    const float* b_ih1 = (const float*)d_in[10];
    const float* b_hh1 = (const float*)d_in[11];
    const float* w_ih2 = (const float*)d_in[12];
    const float* w_hh2 = (const float*)d_in[13];
    const float* b_ih2 = (const float*)d_in[14];
    const float* b_hh2 = (const float*)d_in[15];
    const float* phi_w = (const float*)d_in[16];
    const float* phi_b = (const float*)d_in[17];
    const float* key_w = (const float*)d_in[18];
    const float* key_b = (const float*)d_in[19];
    const float* value_w = (const float*)d_in[20];
    const float* value_b = (const float*)d_in[21];
    const float* out_w = (const float*)d_in[22];
    const float* out_b = (const float*)d_in[23];
    const float* hx0 = (const float*)d_in[24];
    const float* cx0 = (const float*)d_in[25];
    const float* hx1 = (const float*)d_in[26];
    const float* cx1 = (const float*)d_in[27];
    const float* hx2 = (const float*)d_in[28];
    const float* cx2 = (const float*)d_in[29];

    float* out = (float*)d_out;
    float* logits_base = out;                        // [T,B,V]
    float* attn_base   = out + (size_t)TT * BB * VV; // [T,B,L]

    const int smem_bytes = SMEM_FLOATS * 4;
    cudaFuncSetAttribute(speller_persistent,
                         cudaFuncAttributeMaxDynamicSharedMemorySize, smem_bytes);

    pre_kernel<<<4096 + VV + NBLK + 256, 256>>>(
        lf, key_w, key_b, value_w, value_b,
        emb, w_ih0, b_ih0, b_hh0, w_hh0,
        w_ih1, w_hh1, w_ih2, w_hh2,
        b_ih1, b_hh1, b_ih2, b_hh2,
        phi_w, transcript, hx0, hx1, hx2);
    speller_persistent<<<NBLK, NTHR, smem_bytes>>>(
        lens, phi_b, out_w, out_b, cx0, cx1, cx2,
        attn_base, logits_base);
}